// round 1
// baseline (speedup 1.0000x reference)
#include <cuda_runtime.h>

// Problem constants (shape fixed by setup_inputs: [32, 3, 512, 512] fp32 x2)
#define BINS 64
#define ROWS 96              // B*C = 32*3
#define HW   262144          // H*W = 512*512
#define T    128             // threads per histogram block
#define BPR  16              // blocks per row

// Global accumulators: [tensor(2)][row(96)][bin(64)]
__device__ unsigned int g_hist[2 * ROWS * BINS];

__global__ void zero_kernel() {
    int i = blockIdx.x * blockDim.x + threadIdx.x;
    if (i < 2 * ROWS * BINS) g_hist[i] = 0u;
}

__device__ __forceinline__ void bump(unsigned int* cnt, int tid, float x) {
    // torch.histc / reference semantics: clip(x,0,1); idx = clip((int)(x*64), 0, 63)
    float xf = fminf(fmaxf(x, 0.0f), 1.0f);
    int b = (int)(xf * 64.0f);   // cvt.rzi (truncation, matches .astype(int32))
    b = min(b, BINS - 1);
    cnt[b * T + tid] += 1u;      // bank = tid%32 -> conflict-free for any b
}

__global__ __launch_bounds__(T) void hist_kernel(const float* __restrict__ fake,
                                                 const float* __restrict__ real) {
    __shared__ unsigned int cnt[BINS * T];   // 32 KB, per-thread private columns
    const int tid = threadIdx.x;
    const int row = blockIdx.y;
    const float* src = (blockIdx.z == 0) ? fake : real;

    #pragma unroll
    for (int i = tid; i < BINS * T; i += T) cnt[i] = 0u;
    __syncthreads();

    const int n4 = HW / 4 / BPR;  // 4096 float4 per block
    const float4* p = (const float4*)(src + (size_t)row * HW) + (size_t)blockIdx.x * n4;

    // 8 outer iterations; 4 independent float4 loads per iteration for MLP
    #pragma unroll 1
    for (int i = tid; i < n4; i += 4 * T) {
        float4 v0 = p[i];
        float4 v1 = p[i + T];
        float4 v2 = p[i + 2 * T];
        float4 v3 = p[i + 3 * T];
        bump(cnt, tid, v0.x); bump(cnt, tid, v0.y); bump(cnt, tid, v0.z); bump(cnt, tid, v0.w);
        bump(cnt, tid, v1.x); bump(cnt, tid, v1.y); bump(cnt, tid, v1.z); bump(cnt, tid, v1.w);
        bump(cnt, tid, v2.x); bump(cnt, tid, v2.y); bump(cnt, tid, v2.z); bump(cnt, tid, v2.w);
        bump(cnt, tid, v3.x); bump(cnt, tid, v3.y); bump(cnt, tid, v3.z); bump(cnt, tid, v3.w);
    }
    __syncthreads();

    // Tree-reduce the T private columns per bin (log2(T)=7 steps)
    for (int k = 6; k >= 0; --k) {
        int s = 1 << k;
        for (int idx = tid; idx < BINS * s; idx += T) {
            int b = idx >> k;
            int t = idx & (s - 1);
            cnt[b * T + t] += cnt[b * T + t + s];
        }
        __syncthreads();
    }

    if (tid < BINS) {
        atomicAdd(&g_hist[((size_t)blockIdx.z * ROWS + row) * BINS + tid], cnt[tid * T]);
    }
}

__global__ void loss_kernel(float* __restrict__ out) {
    __shared__ int warp_sums[8];
    const int tid = threadIdx.x;
    int sum = 0;
    for (int i = tid; i < ROWS * BINS; i += 256) {
        int a = (int)g_hist[i];
        int b = (int)g_hist[ROWS * BINS + i];
        int d = a - b;
        sum += (d < 0) ? -d : d;
    }
    #pragma unroll
    for (int o = 16; o; o >>= 1) sum += __shfl_xor_sync(0xffffffffu, sum, o);
    if ((tid & 31) == 0) warp_sums[tid >> 5] = sum;
    __syncthreads();
    if (tid == 0) {
        int tot = 0;
        #pragma unroll
        for (int w = 0; w < 8; ++w) tot += warp_sums[w];
        // counts per row always sum to HW exactly -> constant normalizer
        double loss = (double)tot / ((double)HW * (double)(ROWS * BINS));
        out[0] = (float)loss;
    }
}

extern "C" void kernel_launch(void* const* d_in, const int* in_sizes, int n_in,
                              void* d_out, int out_size) {
    const float* fake = (const float*)d_in[0];
    const float* real = (const float*)d_in[1];
    float* out = (float*)d_out;

    zero_kernel<<<(2 * ROWS * BINS + 255) / 256, 256>>>();
    dim3 grid(BPR, ROWS, 2);
    hist_kernel<<<grid, T>>>(fake, real);
    loss_kernel<<<1, 256>>>(out);
}

// round 6
// speedup vs baseline: 1.1799x; 1.1799x over previous
#include <cuda_runtime.h>

// Shape fixed by setup_inputs: [32, 3, 512, 512] fp32 x2
#define BINS 64
#define ROWS 96              // B*C
#define HW   262144          // H*W
#define N4   (HW / 4)        // float4 per row = 65536
#define T    128             // threads per histogram block
#define BPR  10              // blocks per row -> 10*96*2 = 1920 blocks (single wave @ occ>=13)
#define RB   (ROWS * BINS)

// Global accumulators: [tensor(2)][row(96)][bin(64)]
// Zero-initialized at module load; loss_kernel re-zeroes after reading,
// so every graph replay sees zeros (deterministic).
__device__ unsigned int g_hist[2 * RB];

__device__ __forceinline__ void bump(unsigned char* base, int col, float x) {
    // reference: clip(x,0,1); idx = clip(trunc(x*64), 0, 63)
    int b = __float2int_rz(x * 64.0f);
    b = max(b, 0);
    b = min(b, BINS - 1);
    base[(b << 7) + col] += (unsigned char)1;
}

__global__ __launch_bounds__(T, 13) void hist_kernel(const float* __restrict__ fake,
                                                     const float* __restrict__ real) {
    // Two independent sub-histograms -> two pipelined RMW chains.
    // uchar counters: worst case per thread per chain <= ~103 < 255.
    __shared__ unsigned char cA[BINS * T];   // 8 KB
    __shared__ unsigned char cB[BINS * T];   // 8 KB
    const int tid = threadIdx.x;
    const int row = blockIdx.y;
    const float* src = (blockIdx.z == 0) ? fake : real;

    // Zero smem (as words)
    {
        unsigned int* wa = (unsigned int*)cA;
        unsigned int* wb = (unsigned int*)cB;
        #pragma unroll
        for (int i = tid; i < BINS * T / 4; i += T) { wa[i] = 0u; wb[i] = 0u; }
    }
    __syncthreads();

    // Conflict-free byte column: bank = tid&31 for any bin
    const int col = ((tid & 31) << 2) | (tid >> 5);

    const float4* p = (const float4*)(src + (size_t)row * HW);
    const int s = (blockIdx.x * N4) / BPR;
    const int e = ((blockIdx.x + 1) * N4) / BPR;

    int i = s + tid;
    #pragma unroll 1
    for (; i + 3 * T < e; i += 4 * T) {
        float4 v0 = p[i];
        float4 v1 = p[i + T];
        float4 v2 = p[i + 2 * T];
        float4 v3 = p[i + 3 * T];
        bump(cA, col, v0.x); bump(cB, col, v0.y); bump(cA, col, v0.z); bump(cB, col, v0.w);
        bump(cA, col, v1.x); bump(cB, col, v1.y); bump(cA, col, v1.z); bump(cB, col, v1.w);
        bump(cA, col, v2.x); bump(cB, col, v2.y); bump(cA, col, v2.z); bump(cB, col, v2.w);
        bump(cA, col, v3.x); bump(cB, col, v3.y); bump(cA, col, v3.z); bump(cB, col, v3.w);
    }
    #pragma unroll 1
    for (; i < e; i += T) {
        float4 v = p[i];
        bump(cA, col, v.x); bump(cB, col, v.y); bump(cA, col, v.z); bump(cB, col, v.w);
    }
    __syncthreads();

    // Reduce: thread t handles bin b = t>>1, half pp = t&1.
    // Word index rotation (b + 16*pp + w) & 31 keeps banks distinct across the warp.
    const unsigned int* wA = (const unsigned int*)cA;
    const unsigned int* wB = (const unsigned int*)cB;
    const int b  = tid >> 1;
    const int pp = tid & 1;
    unsigned int sum = 0u;
    #pragma unroll
    for (int w = 0; w < 16; ++w) {
        int j = (b + (pp << 4) + w) & 31;
        sum = __dp4a(wA[(b << 5) + j], 0x01010101u, sum);
        sum = __dp4a(wB[(b << 5) + j], 0x01010101u, sum);
    }
    sum += __shfl_xor_sync(0xffffffffu, sum, 1);
    if (pp == 0) {
        atomicAdd(&g_hist[((int)blockIdx.z * ROWS + row) * BINS + b], sum);
    }
}

__global__ void loss_kernel(float* __restrict__ out) {
    __shared__ int warp_sums[8];
    const int tid = threadIdx.x;
    int sum = 0;
    #pragma unroll 1
    for (int i = tid; i < RB; i += 256) {
        int a = (int)g_hist[i];
        int b = (int)g_hist[RB + i];
        int d = a - b;
        sum += (d < 0) ? -d : d;
        // restore zeros for next graph replay
        g_hist[i] = 0u;
        g_hist[RB + i] = 0u;
    }
    #pragma unroll
    for (int o = 16; o; o >>= 1) sum += __shfl_xor_sync(0xffffffffu, sum, o);
    if ((tid & 31) == 0) warp_sums[tid >> 5] = sum;
    __syncthreads();
    if (tid == 0) {
        int tot = 0;
        #pragma unroll
        for (int w = 0; w < 8; ++w) tot += warp_sums[w];
        // counts per row sum to HW exactly -> constant normalizer
        double loss = (double)tot / ((double)HW * (double)(RB));
        out[0] = (float)loss;
    }
}

extern "C" void kernel_launch(void* const* d_in, const int* in_sizes, int n_in,
                              void* d_out, int out_size) {
    const float* fake = (const float*)d_in[0];
    const float* real = (const float*)d_in[1];
    float* out = (float*)d_out;

    dim3 grid(BPR, ROWS, 2);
    hist_kernel<<<grid, T>>>(fake, real);
    loss_kernel<<<1, 256>>>(out);
}